// round 1
// baseline (speedup 1.0000x reference)
#include <cuda_runtime.h>
#include <cuda_bf16.h>
#include <cstdint>

// ---------------------------------------------------------------------------
// StarBlock fused quantized MLP for GB300 (baseline: mma.sync bf16 path)
//
//  x[32768,1024] fp32
//  s1 = x @ w1q^T + b1q ; s2 = x @ w2q^T + b2q        (w*q = round(w*128)/128)
//  a  = clamp(floor(relu(s1)*128), 0,127)             (int)
//  b  = clamp(floor(clip(s2*128,-128,127)), -128,127) (int)
//  h  = clamp((a0*b0 + a1*b1) >> 7, -128, 127) / 128  (exact integer path)
//  out= relu(h @ wdq^T + bdq)
//
// bf16-exactness: round(w*128) in [-128,127] -> k/128 exact in bf16.
// x split into hi+lo bf16 -> K doubled to 2048 with duplicated weights.
// ---------------------------------------------------------------------------

#define B_ROWS 32768
#define DIN    1024
#define DHID   2048
#define DOUT   1024
#define KSPLIT 2048   // 2 * DIN (hi | lo)

// ------------------------- scratch (device globals) ------------------------
__device__ __nv_bfloat16 g_X [(size_t)B_ROWS * KSPLIT];   // 128 MiB: [hi | lo]
__device__ __nv_bfloat16 g_w1[(size_t)DHID   * KSPLIT];   // 8 MiB (duplicated K)
__device__ __nv_bfloat16 g_w2[(size_t)DHID   * KSPLIT];   // 8 MiB
__device__ __nv_bfloat16 g_wd[(size_t)DOUT   * DOUT];     // 2 MiB
__device__ __nv_bfloat16 g_h [(size_t)B_ROWS * DOUT];     // 64 MiB
__device__ float g_b1[DHID];
__device__ float g_b2[DHID];
__device__ float g_bd[DOUT];

// ------------------------------- helpers -----------------------------------
__device__ __forceinline__ uint32_t sw64(uint32_t off) {
    // 64-byte-row swizzle: bits[5:4] ^= bits[8:7]
    return off ^ ((off >> 3) & 0x30);
}

__device__ __forceinline__ void cp16(uint32_t saddr, const void* gptr) {
    asm volatile("cp.async.cg.shared.global [%0], [%1], 16;\n"
                 :: "r"(saddr), "l"(gptr));
}

__device__ __forceinline__ void ldsm4(uint32_t* r, uint32_t addr) {
    asm volatile("ldmatrix.sync.aligned.m8n8.x4.shared.b16 {%0,%1,%2,%3}, [%4];"
                 : "=r"(r[0]), "=r"(r[1]), "=r"(r[2]), "=r"(r[3])
                 : "r"(addr));
}

__device__ __forceinline__ void mma16816(float* c, const uint32_t* a,
                                         uint32_t b0, uint32_t b1) {
    asm volatile(
        "mma.sync.aligned.m16n8k16.row.col.f32.bf16.bf16.f32 "
        "{%0,%1,%2,%3},{%4,%5,%6,%7},{%8,%9},{%0,%1,%2,%3};"
        : "+f"(c[0]), "+f"(c[1]), "+f"(c[2]), "+f"(c[3])
        : "r"(a[0]), "r"(a[1]), "r"(a[2]), "r"(a[3]), "r"(b0), "r"(b1));
}

// integer epilogue for one (s1 pair, s2 pair) -> one h element
__device__ __forceinline__ __nv_bfloat16 make_h(float s1a, float s1b,
                                                float s2a, float s2b) {
    int a0 = (int)floorf(fminf(fmaxf(s1a, 0.f) * 128.f, 127.f));
    int a1 = (int)floorf(fminf(fmaxf(s1b, 0.f) * 128.f, 127.f));
    int q0 = (int)floorf(fminf(fmaxf(s2a * 128.f, -128.f), 127.f));
    int q1 = (int)floorf(fminf(fmaxf(s2b * 128.f, -128.f), 127.f));
    int t  = a0 * q0 + a1 * q1;
    int hq = t >> 7;                       // floor division by 128 (exact)
    hq = hq < -128 ? -128 : (hq > 127 ? 127 : hq);
    return __float2bfloat16((float)hq * 0.0078125f);
}

// ------------------------------ prep kernels -------------------------------
__global__ void prep_weights_kernel(const float* __restrict__ w1,
                                    const float* __restrict__ w2,
                                    const float* __restrict__ wd,
                                    const float* __restrict__ b1,
                                    const float* __restrict__ b2,
                                    const float* __restrict__ bd) {
    int i = blockIdx.x * blockDim.x + threadIdx.x;
    if (i < DHID * DIN) {
        int r = i >> 10, c = i & 1023;
        float q1 = rintf(fminf(fmaxf(w1[i] * 128.f, -128.f), 127.f)) * 0.0078125f;
        float q2 = rintf(fminf(fmaxf(w2[i] * 128.f, -128.f), 127.f)) * 0.0078125f;
        __nv_bfloat16 h1 = __float2bfloat16(q1);
        __nv_bfloat16 h2 = __float2bfloat16(q2);
        size_t base = (size_t)r * KSPLIT + c;
        g_w1[base] = h1; g_w1[base + DIN] = h1;   // duplicated for hi|lo split
        g_w2[base] = h2; g_w2[base + DIN] = h2;
    }
    if (i < DOUT * DOUT) {
        float qd = rintf(fminf(fmaxf(wd[i] * 128.f, -128.f), 127.f)) * 0.0078125f;
        g_wd[i] = __float2bfloat16(qd);
    }
    if (i < DHID) {
        g_b1[i] = rintf(b1[i] * 16384.f) * (1.f / 16384.f);
        g_b2[i] = rintf(b2[i] * 16384.f) * (1.f / 16384.f);
    }
    if (i < DOUT) {
        g_bd[i] = rintf(bd[i] * 16384.f) * (1.f / 16384.f);
    }
}

__global__ void split_x_kernel(const float* __restrict__ x) {
    int i = blockIdx.x * blockDim.x + threadIdx.x;
    if (i < B_ROWS * DIN) {
        int r = i >> 10, c = i & 1023;
        float xf = x[i];
        __nv_bfloat16 hi = __float2bfloat16(xf);
        float res = xf - __bfloat162float(hi);
        __nv_bfloat16 lo = __float2bfloat16(res);
        size_t base = (size_t)r * KSPLIT + c;
        g_X[base]       = hi;
        g_X[base + DIN] = lo;
    }
}

// ------------------------------ up GEMM ------------------------------------
// CTA: M=128 rows of X', N=64 cols of both W1 and W2, BK=32 double-buffered.
// 8 warps: warp_m = wid&3 (32 rows), warp_n = wid>>2 (32 cols).
// Stage layout (bytes): A[128x32bf16]=8192, W1[64x32]=4096, W2=4096 -> 16384.
#define UP_STAGE 16384

__device__ __forceinline__ void up_load_stage(uint32_t sbase, int stg,
                                              int m0, int n0, int k0, int tid) {
    uint32_t sA  = sbase + stg * UP_STAGE;
    uint32_t sW1 = sA + 8192;
    uint32_t sW2 = sA + 12288;
#pragma unroll
    for (int j = 0; j < 2; j++) {           // 512 16B chunks of A
        int idx = tid + j * 256;
        int r = idx >> 2, ck = idx & 3;
        cp16(sA + sw64(r * 64 + ck * 16),
             &g_X[(size_t)(m0 + r) * KSPLIT + k0 + ck * 8]);
    }
    {
        int r = tid >> 2, ck = tid & 3;     // 256 chunks each of W1, W2
        uint32_t off = sw64(r * 64 + ck * 16);
        cp16(sW1 + off, &g_w1[(size_t)(n0 + r) * KSPLIT + k0 + ck * 8]);
        cp16(sW2 + off, &g_w2[(size_t)(n0 + r) * KSPLIT + k0 + ck * 8]);
    }
    asm volatile("cp.async.commit_group;" ::: "memory");
}

__global__ void __launch_bounds__(256) up_gemm_kernel() {
    extern __shared__ char smem[];
    const uint32_t sbase = (uint32_t)__cvta_generic_to_shared(smem);
    const int tid  = threadIdx.x;
    const int lane = tid & 31;
    const int wid  = tid >> 5;
    const int wm   = wid & 3;
    const int wn   = wid >> 2;
    const int m0 = blockIdx.y * 128;
    const int n0 = blockIdx.x * 64;

    float acc1[2][4][4];
    float acc2[2][4][4];
#pragma unroll
    for (int a = 0; a < 2; a++)
#pragma unroll
        for (int b = 0; b < 4; b++)
#pragma unroll
            for (int c = 0; c < 4; c++) { acc1[a][b][c] = 0.f; acc2[a][b][c] = 0.f; }

    const int NK = KSPLIT / 32;   // 64
    up_load_stage(sbase, 0, m0, n0, 0, tid);

    for (int it = 0; it < NK; ++it) {
        const int stg = it & 1;
        if (it + 1 < NK) {
            up_load_stage(sbase, stg ^ 1, m0, n0, (it + 1) * 32, tid);
            asm volatile("cp.async.wait_group 1;" ::: "memory");
        } else {
            asm volatile("cp.async.wait_group 0;" ::: "memory");
        }
        __syncthreads();

        uint32_t sA  = sbase + stg * UP_STAGE;
        uint32_t sW1 = sA + 8192;
        uint32_t sW2 = sA + 12288;

#pragma unroll
        for (int ks = 0; ks < 2; ks++) {
            const int ach = ks * 2 + (lane >> 4);
            uint32_t a[2][4];
#pragma unroll
            for (int mt = 0; mt < 2; mt++) {
                int row = wm * 32 + mt * 16 + (lane & 15);
                ldsm4(a[mt], sA + sw64(row * 64 + ach * 16));
            }
            uint32_t bw1[2][4], bw2[2][4];
#pragma unroll
            for (int np = 0; np < 2; np++) {
                int row = wn * 32 + np * 16 + (lane & 15);
                uint32_t off = sw64(row * 64 + ach * 16);
                ldsm4(bw1[np], sW1 + off);
                ldsm4(bw2[np], sW2 + off);
            }
#pragma unroll
            for (int mt = 0; mt < 2; mt++)
#pragma unroll
                for (int np = 0; np < 2; np++)
#pragma unroll
                    for (int sub = 0; sub < 2; sub++) {
                        int nt = np * 2 + sub;
                        mma16816(acc1[mt][nt], a[mt], bw1[np][sub], bw1[np][sub + 2]);
                        mma16816(acc2[mt][nt], a[mt], bw2[np][sub], bw2[np][sub + 2]);
                    }
        }
        __syncthreads();
    }

    // epilogue: pairs (2t, 2t+1) live in c[0],c[1] (and c[2],c[3] at row+8)
#pragma unroll
    for (int mt = 0; mt < 2; mt++) {
#pragma unroll
        for (int nt = 0; nt < 4; nt++) {
            int n  = n0 + wn * 32 + nt * 8 + (lane & 3) * 2;
            int r0 = m0 + wm * 32 + mt * 16 + (lane >> 2);
            float b1a = g_b1[n], b1b = g_b1[n + 1];
            float b2a = g_b2[n], b2b = g_b2[n + 1];
            int hc = n >> 1;
            g_h[(size_t)r0 * DOUT + hc] =
                make_h(acc1[mt][nt][0] + b1a, acc1[mt][nt][1] + b1b,
                       acc2[mt][nt][0] + b2a, acc2[mt][nt][1] + b2b);
            g_h[(size_t)(r0 + 8) * DOUT + hc] =
                make_h(acc1[mt][nt][2] + b1a, acc1[mt][nt][3] + b1b,
                       acc2[mt][nt][2] + b2a, acc2[mt][nt][3] + b2b);
        }
    }
}

// ------------------------------ down GEMM ----------------------------------
// CTA: M=128, N=64, K=1024, BK=32 double-buffered.
// Stage: A 8192 + W 4096 = 12288 bytes.
#define DN_STAGE 12288

__device__ __forceinline__ void dn_load_stage(uint32_t sbase, int stg,
                                              int m0, int n0, int k0, int tid) {
    uint32_t sA = sbase + stg * DN_STAGE;
    uint32_t sW = sA + 8192;
#pragma unroll
    for (int j = 0; j < 2; j++) {
        int idx = tid + j * 256;
        int r = idx >> 2, ck = idx & 3;
        cp16(sA + sw64(r * 64 + ck * 16),
             &g_h[(size_t)(m0 + r) * DOUT + k0 + ck * 8]);
    }
    {
        int r = tid >> 2, ck = tid & 3;
        cp16(sW + sw64(r * 64 + ck * 16),
             &g_wd[(size_t)(n0 + r) * DOUT + k0 + ck * 8]);
    }
    asm volatile("cp.async.commit_group;" ::: "memory");
}

__global__ void __launch_bounds__(256) down_gemm_kernel(float* __restrict__ out) {
    extern __shared__ char smem[];
    const uint32_t sbase = (uint32_t)__cvta_generic_to_shared(smem);
    const int tid  = threadIdx.x;
    const int lane = tid & 31;
    const int wid  = tid >> 5;
    const int wm   = wid & 3;
    const int wn   = wid >> 2;
    const int m0 = blockIdx.y * 128;
    const int n0 = blockIdx.x * 64;

    float acc[2][4][4];
#pragma unroll
    for (int a = 0; a < 2; a++)
#pragma unroll
        for (int b = 0; b < 4; b++)
#pragma unroll
            for (int c = 0; c < 4; c++) acc[a][b][c] = 0.f;

    const int NK = DOUT / 32;   // 32
    dn_load_stage(sbase, 0, m0, n0, 0, tid);

    for (int it = 0; it < NK; ++it) {
        const int stg = it & 1;
        if (it + 1 < NK) {
            dn_load_stage(sbase, stg ^ 1, m0, n0, (it + 1) * 32, tid);
            asm volatile("cp.async.wait_group 1;" ::: "memory");
        } else {
            asm volatile("cp.async.wait_group 0;" ::: "memory");
        }
        __syncthreads();

        uint32_t sA = sbase + stg * DN_STAGE;
        uint32_t sW = sA + 8192;

#pragma unroll
        for (int ks = 0; ks < 2; ks++) {
            const int ach = ks * 2 + (lane >> 4);
            uint32_t a[2][4];
#pragma unroll
            for (int mt = 0; mt < 2; mt++) {
                int row = wm * 32 + mt * 16 + (lane & 15);
                ldsm4(a[mt], sA + sw64(row * 64 + ach * 16));
            }
            uint32_t bw[2][4];
#pragma unroll
            for (int np = 0; np < 2; np++) {
                int row = wn * 32 + np * 16 + (lane & 15);
                ldsm4(bw[np], sW + sw64(row * 64 + ach * 16));
            }
#pragma unroll
            for (int mt = 0; mt < 2; mt++)
#pragma unroll
                for (int np = 0; np < 2; np++)
#pragma unroll
                    for (int sub = 0; sub < 2; sub++) {
                        int nt = np * 2 + sub;
                        mma16816(acc[mt][nt], a[mt], bw[np][sub], bw[np][sub + 2]);
                    }
        }
        __syncthreads();
    }

#pragma unroll
    for (int mt = 0; mt < 2; mt++) {
#pragma unroll
        for (int nt = 0; nt < 4; nt++) {
            int n  = n0 + wn * 32 + nt * 8 + (lane & 3) * 2;
            int r0 = m0 + wm * 32 + mt * 16 + (lane >> 2);
            float bda = g_bd[n], bdb = g_bd[n + 1];
            out[(size_t)r0 * DOUT + n]           = fmaxf(acc[mt][nt][0] + bda, 0.f);
            out[(size_t)r0 * DOUT + n + 1]       = fmaxf(acc[mt][nt][1] + bdb, 0.f);
            out[(size_t)(r0 + 8) * DOUT + n]     = fmaxf(acc[mt][nt][2] + bda, 0.f);
            out[(size_t)(r0 + 8) * DOUT + n + 1] = fmaxf(acc[mt][nt][3] + bdb, 0.f);
        }
    }
}

// ------------------------------- launch -------------------------------------
extern "C" void kernel_launch(void* const* d_in, const int* in_sizes, int n_in,
                              void* d_out, int out_size) {
    (void)in_sizes; (void)n_in; (void)out_size;
    const float* x  = (const float*)d_in[0];
    const float* w1 = (const float*)d_in[1];
    const float* b1 = (const float*)d_in[2];
    const float* w2 = (const float*)d_in[3];
    const float* b2 = (const float*)d_in[4];
    const float* wd = (const float*)d_in[5];
    const float* bd = (const float*)d_in[6];
    float* out = (float*)d_out;

    prep_weights_kernel<<<(DHID * DIN) / 256, 256>>>(w1, w2, wd, b1, b2, bd);
    split_x_kernel<<<(B_ROWS * DIN) / 256, 256>>>(x);

    dim3 gup(DHID / 64, B_ROWS / 128);     // (32, 256)
    up_gemm_kernel<<<gup, 256, 2 * UP_STAGE>>>();

    dim3 gdn(DOUT / 64, B_ROWS / 128);     // (16, 256)
    down_gemm_kernel<<<gdn, 256, 2 * DN_STAGE>>>(out);
}